// round 5
// baseline (speedup 1.0000x reference)
#include <cuda_runtime.h>

// Problem constants (B=512, F=512, max_depth=8 -> 255 splits, 511 nodes, 21 candidates)
#define BB 512
#define FF 512
#define NS 255
#define NN 511
#define NC 21

// Scratch (device globals; no allocation allowed)
__device__ float d_qnodeB[BB * NN];   // [b][n]
__device__ float d_ga[NN * NC];       // [n][c]
__device__ float d_anode[NN];

// ---------------------------------------------------------------------------
// Kernel 1 (fused): q_split = x @ W + b, then q_node per batch row.
// grid 128, block 256; each block does 4 batch rows; thread s computes split s.
// x rows staged interleaved ([f][r], 16B-aligned) so the 4 row reads per f are
// one LDS.128. Warp reads of W[f*NS+s] are contiguous in s -> coalesced.
// After the GEMM, q_split lives in shared and the q_node ancestor walk
// happens in-block (no global round trip).
// ---------------------------------------------------------------------------
__global__ __launch_bounds__(256) void k_gemm_qnode(const float* __restrict__ x,
                                                    const float* __restrict__ W,
                                                    const float* __restrict__ bias) {
    __shared__ __align__(16) float xs[4 * FF];   // 8 KB: interleaved x, then q_split
    int rb = blockIdx.x * 4;
    // stage x interleaved: xs[f*4 + r] = x[(rb+r)*FF + f]
    for (int i = threadIdx.x; i < 4 * FF; i += 256) {
        int r = i >> 9;          // i / 512
        int f = i & 511;
        xs[f * 4 + r] = x[(rb + r) * FF + f];
    }
    __syncthreads();

    int s = threadIdx.x;
    float a0 = 0.f, a1 = 0.f, a2 = 0.f, a3 = 0.f;
    if (s < NS) {
#pragma unroll 8
        for (int f = 0; f < FF; ++f) {
            float w = W[f * NS + s];
            float4 xv = *reinterpret_cast<const float4*>(&xs[f * 4]);
            a0 = fmaf(xv.x, w, a0);
            a1 = fmaf(xv.y, w, a1);
            a2 = fmaf(xv.z, w, a2);
            a3 = fmaf(xv.w, w, a3);
        }
        float bv = bias[s];
        a0 += bv; a1 += bv; a2 += bv; a3 += bv;
    }
    __syncthreads();   // all xs reads done; reuse as q_split[4][256]
    if (s < NS) {
        xs[0 * 256 + s] = a0;
        xs[1 * 256 + s] = a1;
        xs[2 * 256 + s] = a2;
        xs[3 * 256 + s] = a3;
    }
    __syncthreads();

    // q_node[b][n] = min(1, min over ancestors p of (right-child? +q : -q))
    for (int idx = threadIdx.x; idx < 4 * NN; idx += 256) {
        int r = idx / NN;
        int n = idx - r * NN;
        const float* qs = &xs[r * 256];
        float q = 1.0f;
        int a = n;
        while (a > 0) {
            int p = (a - 1) >> 1;
            float v = qs[p];
            q = fminf(q, (a == 2 * p + 2) ? v : -v);
            a = p;
        }
        d_qnodeB[(rb + r) * NN + n] = q;
    }
}

// ---------------------------------------------------------------------------
// Kernel 2: g_a[n][c] = 0.5*a_c^2 + 0.5 * sum_b [a_c <= q+0.5] (a_c-(q+0.5))^2
// grid 511 (node), block 128 (4 warps; warp w covers batch [w*128,(w+1)*128)).
// Each load is a single-address broadcast to the 21 active lanes; 8 Kahan-
// compensated float chains per warp for MLP (no FP64: B300 FP64 is slow).
// ---------------------------------------------------------------------------
__device__ __forceinline__ void kadd(float& s, float& comp, float v) {
    float y = v - comp;
    float t = s + y;
    comp = (t - s) - y;
    s = t;
}

__global__ __launch_bounds__(128) void k_ga() {
    __shared__ float red_s[4][NC];
    __shared__ float red_c[4][NC];
    int n = blockIdx.x;
    int w = threadIdx.x >> 5;
    int c = threadIdx.x & 31;
    const float* __restrict__ qb = &d_qnodeB[n];   // stride NN over batch
    float ac = (float)c * 0.05f;

    float s0 = 0, s1 = 0, s2 = 0, s3 = 0, s4 = 0, s5 = 0, s6 = 0, s7 = 0;
    float c0 = 0, c1 = 0, c2 = 0, c3 = 0, c4 = 0, c5 = 0, c6 = 0, c7 = 0;
    if (c < NC) {
        int b0 = w * 128;
        for (int b = b0; b < b0 + 128; b += 8) {
            float h0 = qb[(b + 0) * NN] + 0.5f;
            float h1 = qb[(b + 1) * NN] + 0.5f;
            float h2 = qb[(b + 2) * NN] + 0.5f;
            float h3 = qb[(b + 3) * NN] + 0.5f;
            float h4 = qb[(b + 4) * NN] + 0.5f;
            float h5 = qb[(b + 5) * NN] + 0.5f;
            float h6 = qb[(b + 6) * NN] + 0.5f;
            float h7 = qb[(b + 7) * NN] + 0.5f;
            float d0 = ac - h0, d1 = ac - h1, d2 = ac - h2, d3 = ac - h3;
            float d4 = ac - h4, d5 = ac - h5, d6 = ac - h6, d7 = ac - h7;
            if (ac <= h0) kadd(s0, c0, d0 * d0);
            if (ac <= h1) kadd(s1, c1, d1 * d1);
            if (ac <= h2) kadd(s2, c2, d2 * d2);
            if (ac <= h3) kadd(s3, c3, d3 * d3);
            if (ac <= h4) kadd(s4, c4, d4 * d4);
            if (ac <= h5) kadd(s5, c5, d5 * d5);
            if (ac <= h6) kadd(s6, c6, d6 * d6);
            if (ac <= h7) kadd(s7, c7, d7 * d7);
        }
        // combine 8 chains with compensation carried forward
        float S = 0.f, C = 0.f;
        kadd(S, C, s0); kadd(S, C, s1); kadd(S, C, s2); kadd(S, C, s3);
        kadd(S, C, s4); kadd(S, C, s5); kadd(S, C, s6); kadd(S, C, s7);
        // fold chain compensations (they are tiny; plain add is fine)
        C += ((c0 + c1) + (c2 + c3)) + ((c4 + c5) + (c6 + c7));
        red_s[w][c] = S;
        red_c[w][c] = C;
    }
    __syncthreads();
    if (threadIdx.x < NC) {
        int cc = threadIdx.x;
        float S = 0.f, C = 0.f;
        kadd(S, C, red_s[0][cc]); kadd(S, C, red_s[1][cc]);
        kadd(S, C, red_s[2][cc]); kadd(S, C, red_s[3][cc]);
        C += (red_c[0][cc] + red_c[1][cc]) + (red_c[2][cc] + red_c[3][cc]);
        float ssum = S - C;   // Kahan: subtract accumulated compensation
        float acc = (float)cc * 0.05f;
        d_ga[n * NC + cc] = fmaf(0.5f * acc, acc, 0.5f * ssum);
    }
}

// ---------------------------------------------------------------------------
// Kernel 3: the PAV-like scan. Key facts:
//   * n2g rows only get increments (e_par(t) - e_t)  =>  row i = (1-k_i)e_i + k_i e_par(i)
//     with integer k_i (number of times node i was the argmax & merged).
//   * a_node[i] = (1-k_i) a_grp[i] + k_i a_grp[par(i)]
//   * g_grp column updates are incremental: col t -= g_a[t], col par(t) += g_a[t]
//   * once cond==false, state is a fixed point -> early exit.
//   Structure argument: viol[0] == 0 exactly (a_grp[0] snaps to 1.0 under
//   temp-100 softmin with large logit gaps) and initial viols are <= 0, so
//   the expected behavior is freeze at iteration 0. Machinery kept for safety.
// Single block, 512 threads, all state in static shared (<48KB).
// ---------------------------------------------------------------------------
__device__ __forceinline__ float softmin_avg(const float* g) {
    float m = -1e30f;
#pragma unroll
    for (int c = 0; c < NC; ++c) m = fmaxf(m, -100.0f * g[c]);
    float num = 0.f, den = 0.f;
#pragma unroll
    for (int c = 0; c < NC; ++c) {
        float e = __expf(-100.0f * g[c] - m);
        num = fmaf((float)c * 0.05f, e, num);
        den += e;
    }
    return num / den;
}

__global__ __launch_bounds__(512) void k_scan() {
    __shared__ float gg[NN * NC];     // 42924 B
    __shared__ float agrp[NN];
    __shared__ int kk[NN];
    __shared__ float r_val[16];
    __shared__ int r_idx[16];
    __shared__ int sh_t;
    __shared__ int sh_done;

    int tid = threadIdx.x;
    for (int i = tid; i < NN * NC; i += 512) gg[i] = d_ga[i];
    if (tid < NN) kk[tid] = 0;
    __syncthreads();

    if (tid < NN) agrp[tid] = softmin_avg(&gg[tid * NC]);
    __syncthreads();

    const unsigned FULL = 0xffffffffu;
    int i = tid;
    int par = (i > 0) ? ((i - 1) >> 1) : 0;
    int gpar = (par > 0) ? ((par - 1) >> 1) : 0;
    float my_a = 0.0f;

    for (int iter = 0; iter < NN + 1; ++iter) {
        float viol = -1e30f;
        if (i < NN) {
            float ki = (float)kk[i];
            my_a = (1.0f - ki) * agrp[i] + ki * agrp[par];
            float pa;
            if (i == 0) {
                pa = 1.0f;
            } else {
                float kp = (float)kk[par];
                pa = (1.0f - kp) * agrp[par] + kp * agrp[gpar];
            }
            viol = my_a - pa;
        }
        // argmax (tie -> lowest index), warp then block
        float v = viol; int ix = i;
#pragma unroll
        for (int off = 16; off > 0; off >>= 1) {
            float ov = __shfl_down_sync(FULL, v, off);
            int oi = __shfl_down_sync(FULL, ix, off);
            if (ov > v || (ov == v && oi < ix)) { v = ov; ix = oi; }
        }
        if ((tid & 31) == 0) { r_val[tid >> 5] = v; r_idx[tid >> 5] = ix; }
        __syncthreads();
        if (tid < 32) {
            float fv = (tid < 16) ? r_val[tid] : -1e30f;
            int fi = (tid < 16) ? r_idx[tid] : NN;
#pragma unroll
            for (int off = 8; off > 0; off >>= 1) {
                float ov = __shfl_down_sync(FULL, fv, off);
                int oi = __shfl_down_sync(FULL, fi, off);
                if (ov > fv || (ov == fv && oi < fi)) { fv = ov; fi = oi; }
            }
            if (tid == 0) {
                int cond = (fv <= 1e-8f) && (fi > 0);
                sh_done = !cond;
                sh_t = fi;
                if (cond) kk[fi] += 1;   // merge: row fi gains (e_par - e_fi)
            }
        }
        __syncthreads();
        if (sh_done) break;       // fixed point: all remaining iterations no-ops
        if (iter == NN) break;    // last body's merge cannot affect returned a_node

        int t = sh_t;
        int tp = (t - 1) >> 1;
        if (tid < NC) {
            gg[t * NC + tid] -= d_ga[t * NC + tid];
        } else if (tid >= 32 && tid < 32 + NC) {
            int c2 = tid - 32;
            gg[tp * NC + c2] += d_ga[t * NC + c2];
        }
        __syncwarp(FULL);
        if (tid == 0) agrp[t] = softmin_avg(&gg[t * NC]);
        if (tid == 32) agrp[tp] = softmin_avg(&gg[tp * NC]);
        __syncthreads();
    }

    if (i < NN) d_anode[i] = my_a;
}

// ---------------------------------------------------------------------------
// Kernel 4: trajectory = clip(q_node, 0, a_node)
// ---------------------------------------------------------------------------
__global__ __launch_bounds__(256) void k_out(float* __restrict__ out) {
    int idx = blockIdx.x * blockDim.x + threadIdx.x;
    if (idx < BB * NN) {
        int b = idx / NN;
        int n = idx - b * NN;
        float q = d_qnodeB[idx];
        float a = d_anode[n];
        out[idx] = fminf(fmaxf(q, 0.0f), a);
    }
}

extern "C" void kernel_launch(void* const* d_in, const int* in_sizes, int n_in,
                              void* d_out, int out_size) {
    const float* x = (const float*)d_in[0];
    const float* W = (const float*)d_in[1];
    const float* b = (const float*)d_in[2];
    // d_in[3] = max_depth (always 8; constants hardcoded)

    k_gemm_qnode<<<BB / 4, 256>>>(x, W, b);
    k_ga<<<NN, 128>>>();
    k_scan<<<1, 512>>>();
    int tot = BB * NN;
    k_out<<<(tot + 255) / 256, 256>>>((float*)d_out);
}